// round 16
// baseline (speedup 1.0000x reference)
#include <cuda_runtime.h>
#include <cuda_bf16.h>
#include <math.h>
#include <stdint.h>

// Problem constants
#define BB 2
#define TT 2048
#define EE 1024
#define HH 16
#define KVH 4
#define HD 64
#define GG 4           // H / KVH
#define MM (BB*TT)     // 4096 rows

// ---------------------------------------------------------------------------
// Device scratch
// ---------------------------------------------------------------------------
__device__ __nv_bfloat16 g_x_hi[MM*EE],      g_x_lo[MM*EE];
__device__ __nv_bfloat16 g_y_hi[MM*EE],      g_y_lo[MM*EE];
__device__ __nv_bfloat16 g_qh[MM*EE],        g_ql[MM*EE];
__device__ __nv_bfloat16 g_wq_hi[EE*EE],     g_wq_lo[EE*EE];
__device__ __nv_bfloat16 g_wk_hi[KVH*HD*EE], g_wk_lo[KVH*HD*EE];
__device__ __nv_bfloat16 g_wv_hi[KVH*HD*EE], g_wv_lo[KVH*HD*EE];
__device__ __nv_bfloat16 g_wo_hi[EE*EE],     g_wo_lo[EE*EE];

__device__ __nv_bfloat16 g_kh[MM*KVH*HD],    g_kl[MM*KVH*HD];
__device__ __nv_bfloat16 g_vh[MM*KVH*HD],    g_vl[MM*KVH*HD];

// ---------------------------------------------------------------------------
// PTX helpers
// ---------------------------------------------------------------------------
__device__ __forceinline__ uint32_t smem_u32(const void* p) {
    uint32_t a;
    asm("{ .reg .u64 t; cvta.to.shared.u64 t, %1; cvt.u32.u64 %0, t; }"
        : "=r"(a) : "l"(p));
    return a;
}

__device__ __forceinline__ float ex2f(float x) {
    float r;
    asm("ex2.approx.ftz.f32 %0, %1;" : "=f"(r) : "f"(x));
    return r;
}

#define LDSM4(r, addr) \
    asm volatile("ldmatrix.sync.aligned.m8n8.x4.shared.b16 {%0,%1,%2,%3}, [%4];" \
        : "=r"((r)[0]), "=r"((r)[1]), "=r"((r)[2]), "=r"((r)[3]) : "r"(addr))

#define LDSM4T(r, addr) \
    asm volatile("ldmatrix.sync.aligned.m8n8.x4.trans.shared.b16 {%0,%1,%2,%3}, [%4];" \
        : "=r"((r)[0]), "=r"((r)[1]), "=r"((r)[2]), "=r"((r)[3]) : "r"(addr))

#define MMA_BF16(d, a, b) \
    asm volatile("mma.sync.aligned.m16n8k16.row.col.f32.bf16.bf16.f32 " \
        "{%0,%1,%2,%3}, {%4,%5,%6,%7}, {%8,%9}, {%0,%1,%2,%3};" \
        : "+f"((d)[0]), "+f"((d)[1]), "+f"((d)[2]), "+f"((d)[3]) \
        : "r"((a)[0]), "r"((a)[1]), "r"((a)[2]), "r"((a)[3]), \
          "r"((b)[0]), "r"((b)[1]))

#define CP_ASYNC16(dst, src) \
    asm volatile("cp.async.cg.shared.global [%0], [%1], 16;" \
        :: "r"(dst), "l"(src))
#define CP_COMMIT() asm volatile("cp.async.commit_group;" ::: "memory")
#define CP_WAIT0()  asm volatile("cp.async.wait_group 0;" ::: "memory")
#define CP_WAIT1()  asm volatile("cp.async.wait_group 1;" ::: "memory")

__device__ __forceinline__ uint32_t pack_bf16(float lo, float hi) {
    __nv_bfloat162 t = __float22bfloat162_rn(make_float2(lo, hi));
    return *reinterpret_cast<uint32_t*>(&t);
}

__device__ __forceinline__ void pack_split(float v0, float v1,
                                           uint32_t& ph, uint32_t& pl) {
    ph = pack_bf16(v0, v1);
    __nv_bfloat162 hb = *reinterpret_cast<__nv_bfloat162*>(&ph);
    pl = pack_bf16(v0 - __bfloat162float(hb.x), v1 - __bfloat162float(hb.y));
}

// ---------------------------------------------------------------------------
// Splits
// ---------------------------------------------------------------------------
struct SplitArgs {
    const float*   in[4];
    __nv_bfloat16* hi[4];
    __nv_bfloat16* lo[4];
    int            n4[4];
};

__device__ __forceinline__ void split_one(const float* __restrict__ in,
                                          __nv_bfloat16* __restrict__ hi,
                                          __nv_bfloat16* __restrict__ lo, int i)
{
    float4 v = reinterpret_cast<const float4*>(in)[i];
    uint32_t ph0, pl0, ph1, pl1;
    pack_split(v.x, v.y, ph0, pl0);
    pack_split(v.z, v.w, ph1, pl1);
    reinterpret_cast<uint2*>(hi)[i] = make_uint2(ph0, ph1);
    reinterpret_cast<uint2*>(lo)[i] = make_uint2(pl0, pl1);
}

__global__ void split_w(SplitArgs a)
{
    int seg = blockIdx.y;
    int i   = blockIdx.x * blockDim.x + threadIdx.x;
    if (i >= a.n4[seg]) return;
    split_one(a.in[seg], a.hi[seg], a.lo[seg], i);
}

__global__ void split_x(const float* __restrict__ in,
                        __nv_bfloat16* __restrict__ hi,
                        __nv_bfloat16* __restrict__ lo, int n4)
{
    int i = blockIdx.x * blockDim.x + threadIdx.x;
    if (i >= n4) return;
    split_one(in, hi, lo, i);
}

// ---------------------------------------------------------------------------
// mma.sync GEMM body: 256 threads, 8 warps 2x4, warp tile 64x32.
// Epilogues: fp32 C | bf16 hi/lo split | RoPE(+scale) + bf16 hi/lo split.
// ---------------------------------------------------------------------------
#define TILE_BYTES   10240
#define BUF_BYTES    (4*TILE_BYTES)
#define GEMM_SMEM    (2*BUF_BYTES)

#define SCALE_L2E 0.180336879f         // 0.125 * log2(e)

__device__ __forceinline__ void issue_tile(
    uint32_t sbuf,
    const __nv_bfloat16* __restrict__ Ahi, const __nv_bfloat16* __restrict__ Alo,
    const __nv_bfloat16* __restrict__ Bhi, const __nv_bfloat16* __restrict__ Blo,
    int m0, int n0, int k0, int K, int tid)
{
    #pragma unroll
    for (int it = 0; it < 2; it++) {
        int idx = tid + it * 256;
        int r   = idx >> 2;
        int c8  = idx & 3;
        uint32_t so = (uint32_t)(r * 80 + c8 * 16);
        size_t ga = (size_t)(m0 + r) * K + k0 + c8 * 8;
        size_t gb = (size_t)(n0 + r) * K + k0 + c8 * 8;
        CP_ASYNC16(sbuf + so,                 (const char*)(Ahi + ga));
        CP_ASYNC16(sbuf + TILE_BYTES + so,    (const char*)(Alo + ga));
        CP_ASYNC16(sbuf + 2*TILE_BYTES + so,  (const char*)(Bhi + gb));
        CP_ASYNC16(sbuf + 3*TILE_BYTES + so,  (const char*)(Blo + gb));
    }
}

__device__ __forceinline__ void gemm_body(
    char* smp,
    const __nv_bfloat16* __restrict__ Ahi, const __nv_bfloat16* __restrict__ Alo,
    const __nv_bfloat16* __restrict__ Bhi, const __nv_bfloat16* __restrict__ Blo,
    float* __restrict__ C,
    __nv_bfloat16* __restrict__ Ch, __nv_bfloat16* __restrict__ Cl,
    const float* __restrict__ rope_cs, const float* __restrict__ rope_sn,
    float rope_scale,
    int M, int N, int K, int m0, int n0)
{
    const uint32_t sbase = smem_u32(smp);
    const int tid  = threadIdx.x;
    const int lane = tid & 31;
    const int wid  = tid >> 5;
    const int wm   = wid >> 2;
    const int wn   = wid & 3;

    float acc[4][4][4];
    #pragma unroll
    for (int i = 0; i < 4; i++)
        #pragma unroll
        for (int j = 0; j < 4; j++)
            #pragma unroll
            for (int r = 0; r < 4; r++) acc[i][j][r] = 0.f;

    const uint32_t a_row  = (uint32_t)(wm * 64 + (lane & 15));
    const uint32_t a_k8   = (uint32_t)(lane >> 4);
    const uint32_t b_row  = (uint32_t)(wn * 32 + (lane & 7) + ((lane >> 4) << 3));
    const uint32_t b_k8   = (uint32_t)((lane >> 3) & 1);

    const int NK = K / 32;
    issue_tile(sbase, Ahi, Alo, Bhi, Blo, m0, n0, 0, K, tid);
    CP_COMMIT();

    for (int kt = 0; kt < NK; kt++) {
        CP_WAIT0();
        __syncthreads();
        if (kt + 1 < NK) {
            issue_tile(sbase + (uint32_t)((kt + 1) & 1) * BUF_BYTES,
                       Ahi, Alo, Bhi, Blo, m0, n0, (kt + 1) * 32, K, tid);
            CP_COMMIT();
        }
        const uint32_t buf = sbase + (uint32_t)(kt & 1) * BUF_BYTES;

        #pragma unroll
        for (int ks = 0; ks < 2; ks++) {
            uint32_t ah[4][4], al[4][4], bh[2][4], bl[2][4];
            #pragma unroll
            for (int mb = 0; mb < 4; mb++) {
                uint32_t addr = buf + (a_row + mb * 16) * 80
                                    + (ks * 2 + a_k8) * 16;
                LDSM4(ah[mb], addr);
                LDSM4(al[mb], addr + TILE_BYTES);
            }
            #pragma unroll
            for (int nb = 0; nb < 2; nb++) {
                uint32_t addr = buf + 2*TILE_BYTES
                                    + (b_row + nb * 16) * 80
                                    + (ks * 2 + b_k8) * 16;
                LDSM4(bh[nb], addr);
                LDSM4(bl[nb], addr + TILE_BYTES);
            }
            #pragma unroll
            for (int mb = 0; mb < 4; mb++) {
                #pragma unroll
                for (int n8 = 0; n8 < 4; n8++) {
                    uint32_t* Bh = &bh[n8 >> 1][(n8 & 1) * 2];
                    uint32_t* Bl = &bl[n8 >> 1][(n8 & 1) * 2];
                    MMA_BF16(acc[mb][n8], ah[mb], Bh);
                    MMA_BF16(acc[mb][n8], ah[mb], Bl);
                    MMA_BF16(acc[mb][n8], al[mb], Bh);
                }
            }
        }
    }

    if (rope_cs) {
        // RoPE epilogue: stage fp32 to smem, pair d <-> d+32, scale, split
        float* stage = reinterpret_cast<float*>(smp);
        __syncthreads();
        #pragma unroll
        for (int mb = 0; mb < 4; mb++) {
            int lr = wm * 64 + mb * 16 + (lane >> 2);
            #pragma unroll
            for (int n8 = 0; n8 < 4; n8++) {
                int lc = wn * 32 + n8 * 8 + (lane & 3) * 2;
                stage[lr * 132 + lc]       = acc[mb][n8][0];
                stage[lr * 132 + lc + 1]   = acc[mb][n8][1];
                stage[(lr + 8) * 132 + lc]     = acc[mb][n8][2];
                stage[(lr + 8) * 132 + lc + 1] = acc[mb][n8][3];
            }
        }
        __syncthreads();
        {
            int r    = tid >> 1;
            int hsel = tid & 1;
            int rowg = m0 + r;
            const float* srow = stage + r * 132 + hsel * 64;
            size_t crow  = (size_t)rowg * 64;
            size_t obase = (size_t)rowg * N + n0 + hsel * 64;
            #pragma unroll
            for (int j = 0; j < 8; j++) {
                float4 x1 = *reinterpret_cast<const float4*>(srow + 4 * j);
                float4 x2 = *reinterpret_cast<const float4*>(srow + 32 + 4 * j);
                float4 c1 = *reinterpret_cast<const float4*>(rope_cs + crow + 4 * j);
                float4 c2 = *reinterpret_cast<const float4*>(rope_cs + crow + 32 + 4 * j);
                float4 z1 = *reinterpret_cast<const float4*>(rope_sn + crow + 4 * j);
                float4 z2 = *reinterpret_cast<const float4*>(rope_sn + crow + 32 + 4 * j);
                float y1[4] = { (x1.x*c1.x - x2.x*z1.x) * rope_scale,
                                (x1.y*c1.y - x2.y*z1.y) * rope_scale,
                                (x1.z*c1.z - x2.z*z1.z) * rope_scale,
                                (x1.w*c1.w - x2.w*z1.w) * rope_scale };
                float y2[4] = { (x2.x*c2.x + x1.x*z2.x) * rope_scale,
                                (x2.y*c2.y + x1.y*z2.y) * rope_scale,
                                (x2.z*c2.z + x1.z*z2.z) * rope_scale,
                                (x2.w*c2.w + x1.w*z2.w) * rope_scale };
                uint32_t ph, pl;
                pack_split(y1[0], y1[1], ph, pl);
                *reinterpret_cast<uint32_t*>(&Ch[obase + 4*j])     = ph;
                *reinterpret_cast<uint32_t*>(&Cl[obase + 4*j])     = pl;
                pack_split(y1[2], y1[3], ph, pl);
                *reinterpret_cast<uint32_t*>(&Ch[obase + 4*j + 2]) = ph;
                *reinterpret_cast<uint32_t*>(&Cl[obase + 4*j + 2]) = pl;
                pack_split(y2[0], y2[1], ph, pl);
                *reinterpret_cast<uint32_t*>(&Ch[obase + 32 + 4*j])     = ph;
                *reinterpret_cast<uint32_t*>(&Cl[obase + 32 + 4*j])     = pl;
                pack_split(y2[2], y2[3], ph, pl);
                *reinterpret_cast<uint32_t*>(&Ch[obase + 32 + 4*j + 2]) = ph;
                *reinterpret_cast<uint32_t*>(&Cl[obase + 32 + 4*j + 2]) = pl;
            }
        }
    } else if (Ch) {
        #pragma unroll
        for (int mb = 0; mb < 4; mb++) {
            int row = m0 + wm * 64 + mb * 16 + (lane >> 2);
            #pragma unroll
            for (int n8 = 0; n8 < 4; n8++) {
                int col = n0 + wn * 32 + n8 * 8 + (lane & 3) * 2;
                uint32_t ph, pl;
                pack_split(acc[mb][n8][0], acc[mb][n8][1], ph, pl);
                *reinterpret_cast<uint32_t*>(&Ch[(size_t)row * N + col]) = ph;
                *reinterpret_cast<uint32_t*>(&Cl[(size_t)row * N + col]) = pl;
                pack_split(acc[mb][n8][2], acc[mb][n8][3], ph, pl);
                *reinterpret_cast<uint32_t*>(&Ch[(size_t)(row + 8) * N + col]) = ph;
                *reinterpret_cast<uint32_t*>(&Cl[(size_t)(row + 8) * N + col]) = pl;
            }
        }
    } else {
        #pragma unroll
        for (int mb = 0; mb < 4; mb++) {
            int row = m0 + wm * 64 + mb * 16 + (lane >> 2);
            #pragma unroll
            for (int n8 = 0; n8 < 4; n8++) {
                int col = n0 + wn * 32 + n8 * 8 + (lane & 3) * 2;
                *reinterpret_cast<float2*>(&C[(size_t)row * N + col]) =
                    make_float2(acc[mb][n8][0], acc[mb][n8][1]);
                *reinterpret_cast<float2*>(&C[(size_t)(row + 8) * N + col]) =
                    make_float2(acc[mb][n8][2], acc[mb][n8][3]);
            }
        }
    }
}

__global__ __launch_bounds__(256, 2) void gemm_mma(
    const __nv_bfloat16* __restrict__ Ahi, const __nv_bfloat16* __restrict__ Alo,
    const __nv_bfloat16* __restrict__ Bhi, const __nv_bfloat16* __restrict__ Blo,
    float* __restrict__ C, int M, int N, int K)
{
    extern __shared__ char sm[];
    gemm_body(sm, Ahi, Alo, Bhi, Blo, C, nullptr, nullptr, nullptr, nullptr,
              1.f, M, N, K, blockIdx.y * 128, blockIdx.x * 128);
}

// Q: rope(+scale)+split epilogue; K: rope+split; V: split
__global__ __launch_bounds__(256, 2) void gemm_mma_qkv(
    const __nv_bfloat16* __restrict__ Ahi, const __nv_bfloat16* __restrict__ Alo,
    const __nv_bfloat16* __restrict__ Wqh, const __nv_bfloat16* __restrict__ Wql,
    const __nv_bfloat16* __restrict__ Wkh, const __nv_bfloat16* __restrict__ Wkl,
    const __nv_bfloat16* __restrict__ Wvh, const __nv_bfloat16* __restrict__ Wvl,
    const float* __restrict__ cs, const float* __restrict__ sn,
    __nv_bfloat16* __restrict__ Qh, __nv_bfloat16* __restrict__ Ql,
    __nv_bfloat16* __restrict__ Kh, __nv_bfloat16* __restrict__ Kl,
    __nv_bfloat16* __restrict__ Vh, __nv_bfloat16* __restrict__ Vl)
{
    extern __shared__ char sm[];
    int bx = blockIdx.x;
    if (bx < 8) {
        gemm_body(sm, Ahi, Alo, Wqh, Wql, nullptr, Qh, Ql, cs, sn, SCALE_L2E,
                  MM, EE, EE, blockIdx.y * 128, bx * 128);
    } else if (bx < 10) {
        gemm_body(sm, Ahi, Alo, Wkh, Wkl, nullptr, Kh, Kl, cs, sn, 1.f,
                  MM, KVH * HD, EE, blockIdx.y * 128, (bx - 8) * 128);
    } else {
        gemm_body(sm, Ahi, Alo, Wvh, Wvl, nullptr, Vh, Vl, nullptr, nullptr,
                  1.f, MM, KVH * HD, EE, blockIdx.y * 128, (bx - 10) * 128);
    }
}

// ---------------------------------------------------------------------------
// Flash attention: 1 head/CTA, bf16 hi/lo split, 4 warps, 3 CTAs/SM.
// Q pre-scaled by SCALE_L2E (rope fused in GEMM). No-max base-2 softmax
// (MUFU ex2). l-reduction deferred to epilogue.
// ---------------------------------------------------------------------------
#define FROW      144
#define FARR      (64*FROW)
#define KVBUF     (4*FARR)
#define OFF_KH    0
#define OFF_KL    FARR
#define OFF_VH    (2*FARR)
#define OFF_VL    (3*FARR)
#define SM_QH     KVBUF                // bf16 hi; lo at +FARR (buffer-1 overlay)
#define FLASH_SMEM (8*FARR)            // 73728; 3 CTAs/SM

__device__ __forceinline__ void flash_load_kv(
    uint32_t kb,
    const __nv_bfloat16* __restrict__ kh, const __nv_bfloat16* __restrict__ kl,
    const __nv_bfloat16* __restrict__ vh, const __nv_bfloat16* __restrict__ vl,
    int b, int kt, int kvh, int tid)
{
    #pragma unroll
    for (int it = 0; it < 4; it++) {
        int idx = tid + it * 128;
        int r   = idx >> 3;
        int c   = idx & 7;
        size_t g = (size_t)(b * TT + kt * 64 + r) * (KVH * HD) + kvh * 64 + c * 8;
        uint32_t so = (uint32_t)(r * FROW + c * 16);
        CP_ASYNC16(kb + OFF_KH + so, (const char*)(kh + g));
        CP_ASYNC16(kb + OFF_KL + so, (const char*)(kl + g));
        CP_ASYNC16(kb + OFF_VH + so, (const char*)(vh + g));
        CP_ASYNC16(kb + OFF_VL + so, (const char*)(vl + g));
    }
}

__global__ __launch_bounds__(128, 3) void flash_mma(
    const __nv_bfloat16* __restrict__ qh, const __nv_bfloat16* __restrict__ ql,
    const __nv_bfloat16* __restrict__ kh, const __nv_bfloat16* __restrict__ kl,
    const __nv_bfloat16* __restrict__ vh, const __nv_bfloat16* __restrict__ vl,
    __nv_bfloat16* __restrict__ yh, __nv_bfloat16* __restrict__ yl)
{
    extern __shared__ char sm[];
    const uint32_t sb = smem_u32(sm);
    const int tid  = threadIdx.x;
    const int lane = tid & 31;
    const int wid  = tid >> 5;
    const int qt   = (int)(gridDim.x - 1 - blockIdx.x);
    const int h    = blockIdx.y;
    const int b    = blockIdx.z;
    const int kvh  = h / GG;

    // prologue: Q (hi+lo) group, then KV tile 0 group
    #pragma unroll
    for (int it = 0; it < 4; it++) {
        int idx = tid + it * 128;
        int r   = idx >> 3;
        int c   = idx & 7;
        size_t g = (size_t)(b * TT + qt * 64 + r) * EE + h * 64 + c * 8;
        uint32_t so = (uint32_t)(r * FROW + c * 16);
        CP_ASYNC16(sb + SM_QH + so, (const char*)(qh + g));
        CP_ASYNC16(sb + SM_QH + FARR + so, (const char*)(ql + g));
    }
    CP_COMMIT();
    flash_load_kv(sb, kh, kl, vh, vl, b, 0, kvh, tid);
    CP_COMMIT();

    CP_WAIT1();          // Q group complete
    __syncthreads();

    uint32_t qfh[4][4], qfl[4][4];
    {
        const uint32_t a_row = (uint32_t)(wid * 16 + (lane & 15));
        const uint32_t a_k8  = (uint32_t)(lane >> 4);
        #pragma unroll
        for (int ks = 0; ks < 4; ks++) {
            uint32_t addr = sb + SM_QH + a_row * FROW + (ks * 2 + a_k8) * 16;
            LDSM4(qfh[ks], addr);
            LDSM4(qfl[ks], addr + FARR);
        }
    }
    __syncthreads();     // buffer-1 region free after this

    const uint32_t kb_row = (uint32_t)((lane & 7) + ((lane >> 4) << 3));
    const uint32_t kb_k8  = (uint32_t)((lane >> 3) & 1);
    const uint32_t vb_row = (uint32_t)((lane & 7) + (((lane >> 3) & 1) << 3));
    const uint32_t vb_col = (uint32_t)((lane >> 4) << 3);

    float oacc[8][4];
    #pragma unroll
    for (int nb = 0; nb < 8; nb++)
        #pragma unroll
        for (int j = 0; j < 4; j++) oacc[nb][j] = 0.f;
    float l0p = 0.f, l1p = 0.f;      // per-thread partials; reduce at end

    int cur = 0;
    for (int kt = 0; kt <= qt; kt++) {
        if (kt + 1 <= qt) {
            flash_load_kv(sb + (uint32_t)(cur ^ 1) * KVBUF,
                          kh, kl, vh, vl, b, kt + 1, kvh, tid);
            CP_COMMIT();
            CP_WAIT1();
        } else {
            CP_WAIT0();
        }
        __syncthreads();
        const uint32_t kvb = sb + (uint32_t)cur * KVBUF;
        const bool diag = (kt == qt);

        float sacc[8][4];
        #pragma unroll
        for (int nb = 0; nb < 8; nb++)
            #pragma unroll
            for (int j = 0; j < 4; j++) sacc[nb][j] = 0.f;

        #pragma unroll
        for (int ks = 0; ks < 4; ks++) {
            #pragma unroll
            for (int nb = 0; nb < 4; nb++) {
                if (diag && nb > wid) continue;
                uint32_t addr = kvb + OFF_KH + (kb_row + nb * 16) * FROW
                                            + (ks * 2 + kb_k8) * 16;
                uint32_t bh[4], bl[4];
                LDSM4(bh, addr);
                LDSM4(bl, addr + FARR);
                MMA_BF16(sacc[2*nb],   qfh[ks], bh);
                MMA_BF16(sacc[2*nb+1], qfh[ks], bh + 2);
                MMA_BF16(sacc[2*nb],   qfh[ks], bl);
                MMA_BF16(sacc[2*nb+1], qfh[ks], bl + 2);
                MMA_BF16(sacc[2*nb],   qfl[ks], bh);
                MMA_BF16(sacc[2*nb+1], qfl[ks], bh + 2);
            }
        }

        // causal mask (S already base-2 scaled via pre-scaled Q)
        if (diag) {
            #pragma unroll
            for (int nb = 0; nb < 8; nb++)
                #pragma unroll
                for (int j = 0; j < 4; j++) {
                    int n_loc = nb * 8 + 2 * (lane & 3) + (j & 1);
                    int m_loc = wid * 16 + (lane >> 2) + ((j >> 1) << 3);
                    if (n_loc > m_loc) sacc[nb][j] = -1e30f;
                }
        }

        // no-max softmax: exp2 + per-thread partial sums (no shuffles here)
        float sum0 = 0.f, sum1 = 0.f;
        #pragma unroll
        for (int nb = 0; nb < 8; nb++) {
            sacc[nb][0] = ex2f(sacc[nb][0]);
            sacc[nb][1] = ex2f(sacc[nb][1]);
            sacc[nb][2] = ex2f(sacc[nb][2]);
            sacc[nb][3] = ex2f(sacc[nb][3]);
            sum0 += sacc[nb][0] + sacc[nb][1];
            sum1 += sacc[nb][2] + sacc[nb][3];
        }
        l0p += sum0;
        l1p += sum1;

        // streamed pack + PV
        #pragma unroll
        for (int j16 = 0; j16 < 4; j16++) {
            if (diag && j16 > wid) continue;
            uint32_t pfh[4], pfl[4];
            {
                float* c0 = sacc[2*j16];
                float* c1 = sacc[2*j16 + 1];
                #pragma unroll
                for (int a = 0; a < 4; a++) {
                    float v0 = (a < 2) ? c0[(a & 1) * 2]     : c1[(a & 1) * 2];
                    float v1 = (a < 2) ? c0[(a & 1) * 2 + 1] : c1[(a & 1) * 2 + 1];
                    pack_split(v0, v1, pfh[a], pfl[a]);
                }
            }
            #pragma unroll
            for (int nb = 0; nb < 4; nb++) {
                uint32_t addr = kvb + OFF_VH
                              + (j16 * 16 + vb_row) * FROW
                              + (nb * 16 + vb_col) * 2;
                uint32_t vhf[4], vlf[4];
                LDSM4T(vhf, addr);
                LDSM4T(vlf, addr + FARR);
                MMA_BF16(oacc[2*nb],   pfh, vhf);
                MMA_BF16(oacc[2*nb+1], pfh, vhf + 2);
                MMA_BF16(oacc[2*nb],   pfh, vlf);
                MMA_BF16(oacc[2*nb+1], pfh, vlf + 2);
                MMA_BF16(oacc[2*nb],   pfl, vhf);
                MMA_BF16(oacc[2*nb+1], pfl, vhf + 2);
            }
        }

        __syncthreads();
        cur ^= 1;
    }

    // deferred l reduction (once)
    l0p += __shfl_xor_sync(0xffffffffu, l0p, 1);
    l0p += __shfl_xor_sync(0xffffffffu, l0p, 2);
    l1p += __shfl_xor_sync(0xffffffffu, l1p, 1);
    l1p += __shfl_xor_sync(0xffffffffu, l1p, 2);

    float inv0 = 1.f / l0p, inv1 = 1.f / l1p;
    size_t row0 = (size_t)(b * TT + qt * 64 + wid * 16 + (lane >> 2));
    #pragma unroll
    for (int nb = 0; nb < 8; nb++) {
        size_t col = (size_t)(h * 64 + nb * 8 + 2 * (lane & 3));
        uint32_t ph, pl;
        pack_split(oacc[nb][0] * inv0, oacc[nb][1] * inv0, ph, pl);
        *reinterpret_cast<uint32_t*>(&yh[row0 * EE + col]) = ph;
        *reinterpret_cast<uint32_t*>(&yl[row0 * EE + col]) = pl;
        pack_split(oacc[nb][2] * inv1, oacc[nb][3] * inv1, ph, pl);
        *reinterpret_cast<uint32_t*>(&yh[(row0 + 8) * EE + col]) = ph;
        *reinterpret_cast<uint32_t*>(&yl[(row0 + 8) * EE + col]) = pl;
    }
}

// ---------------------------------------------------------------------------
// kernel_launch — 5 launches; flash is #4 (profiler window)
// ---------------------------------------------------------------------------
extern "C" void kernel_launch(void* const* d_in, const int* in_sizes, int n_in,
                              void* d_out, int out_size)
{
    const float* x   = (const float*)d_in[0];
    const float* cs  = (const float*)d_in[1];
    const float* sn  = (const float*)d_in[2];
    const float* Wq  = (const float*)d_in[3];
    const float* Wk  = (const float*)d_in[4];
    const float* Wv  = (const float*)d_in[5];
    const float* Wo  = (const float*)d_in[6];
    float* out = (float*)d_out;

    __nv_bfloat16 *xh, *xl, *yh, *yl, *qhp, *qlp;
    __nv_bfloat16 *wqh, *wql, *wkh, *wkl, *wvh, *wvl, *woh, *wol;
    __nv_bfloat16 *khp, *klp, *vhp, *vlp;
    cudaGetSymbolAddress((void**)&xh,  g_x_hi);  cudaGetSymbolAddress((void**)&xl,  g_x_lo);
    cudaGetSymbolAddress((void**)&yh,  g_y_hi);  cudaGetSymbolAddress((void**)&yl,  g_y_lo);
    cudaGetSymbolAddress((void**)&qhp, g_qh);    cudaGetSymbolAddress((void**)&qlp, g_ql);
    cudaGetSymbolAddress((void**)&wqh, g_wq_hi); cudaGetSymbolAddress((void**)&wql, g_wq_lo);
    cudaGetSymbolAddress((void**)&wkh, g_wk_hi); cudaGetSymbolAddress((void**)&wkl, g_wk_lo);
    cudaGetSymbolAddress((void**)&wvh, g_wv_hi); cudaGetSymbolAddress((void**)&wvl, g_wv_lo);
    cudaGetSymbolAddress((void**)&woh, g_wo_hi); cudaGetSymbolAddress((void**)&wol, g_wo_lo);
    cudaGetSymbolAddress((void**)&khp, g_kh);    cudaGetSymbolAddress((void**)&klp, g_kl);
    cudaGetSymbolAddress((void**)&vhp, g_vh);    cudaGetSymbolAddress((void**)&vlp, g_vl);

    cudaFuncSetAttribute(gemm_mma, cudaFuncAttributeMaxDynamicSharedMemorySize,
                         GEMM_SMEM);
    cudaFuncSetAttribute(gemm_mma_qkv, cudaFuncAttributeMaxDynamicSharedMemorySize,
                         GEMM_SMEM);
    cudaFuncSetAttribute(flash_mma, cudaFuncAttributeMaxDynamicSharedMemorySize,
                         FLASH_SMEM);

    // #1: weight splits
    {
        SplitArgs a;
        a.in[0] = Wq; a.hi[0] = wqh; a.lo[0] = wql; a.n4[0] = EE * EE / 4;
        a.in[1] = Wk; a.hi[1] = wkh; a.lo[1] = wkl; a.n4[1] = KVH * HD * EE / 4;
        a.in[2] = Wv; a.hi[2] = wvh; a.lo[2] = wvl; a.n4[2] = KVH * HD * EE / 4;
        a.in[3] = Wo; a.hi[3] = woh; a.lo[3] = wol; a.n4[3] = EE * EE / 4;
        int maxb = (EE * EE / 4 + 255) / 256;
        split_w<<<dim3(maxb, 4), 256>>>(a);
    }

    // #2: x split
    {
        int n4 = MM * EE / 4;
        split_x<<<(n4 + 255) / 256, 256>>>(x, xh, xl, n4);
    }

    // #3: Q + K + V projections (Q: rope*scale+split; K: rope+split; V: split)
    gemm_mma_qkv<<<dim3(12, MM / 128), 256, GEMM_SMEM>>>(
        xh, xl, wqh, wql, wkh, wkl, wvh, wvl, cs, sn,
        qhp, qlp, khp, klp, vhp, vlp);

    // #4: flash attention — profiler window
    flash_mma<<<dim3(TT / 64, HH, BB), 128, FLASH_SMEM>>>(
        qhp, qlp, khp, klp, vhp, vlp, yh, yl);

    // #5: output projection
    gemm_mma<<<dim3(EE / 128, MM / 128), 256, GEMM_SMEM>>>(yh, yl, woh, wol, out, MM, EE, EE);
}

// round 17
// speedup vs baseline: 1.0642x; 1.0642x over previous
#include <cuda_runtime.h>
#include <cuda_bf16.h>
#include <math.h>
#include <stdint.h>

// Problem constants
#define BB 2
#define TT 2048
#define EE 1024
#define HH 16
#define KVH 4
#define HD 64
#define GG 4           // H / KVH
#define MM (BB*TT)     // 4096 rows

// ---------------------------------------------------------------------------
// Device scratch
// ---------------------------------------------------------------------------
__device__ float g_q[MM*EE];            // fp32 q (rope fused into flash)
__device__ float g_k[MM*KVH*HD];        // fp32 k (rope_k reads)

__device__ __nv_bfloat16 g_x_hi[MM*EE],      g_x_lo[MM*EE];
__device__ __nv_bfloat16 g_y_hi[MM*EE],      g_y_lo[MM*EE];
__device__ __nv_bfloat16 g_wq_hi[EE*EE],     g_wq_lo[EE*EE];
__device__ __nv_bfloat16 g_wk_hi[KVH*HD*EE], g_wk_lo[KVH*HD*EE];
__device__ __nv_bfloat16 g_wv_hi[KVH*HD*EE], g_wv_lo[KVH*HD*EE];
__device__ __nv_bfloat16 g_wo_hi[EE*EE],     g_wo_lo[EE*EE];

__device__ __nv_bfloat16 g_kh[MM*KVH*HD],    g_kl[MM*KVH*HD];
__device__ __nv_bfloat16 g_vh[MM*KVH*HD],    g_vl[MM*KVH*HD];

// ---------------------------------------------------------------------------
// PTX helpers
// ---------------------------------------------------------------------------
__device__ __forceinline__ uint32_t smem_u32(const void* p) {
    uint32_t a;
    asm("{ .reg .u64 t; cvta.to.shared.u64 t, %1; cvt.u32.u64 %0, t; }"
        : "=r"(a) : "l"(p));
    return a;
}

__device__ __forceinline__ float ex2f(float x) {
    float r;
    asm("ex2.approx.ftz.f32 %0, %1;" : "=f"(r) : "f"(x));
    return r;
}

#define LDSM4(r, addr) \
    asm volatile("ldmatrix.sync.aligned.m8n8.x4.shared.b16 {%0,%1,%2,%3}, [%4];" \
        : "=r"((r)[0]), "=r"((r)[1]), "=r"((r)[2]), "=r"((r)[3]) : "r"(addr))

#define LDSM4T(r, addr) \
    asm volatile("ldmatrix.sync.aligned.m8n8.x4.trans.shared.b16 {%0,%1,%2,%3}, [%4];" \
        : "=r"((r)[0]), "=r"((r)[1]), "=r"((r)[2]), "=r"((r)[3]) : "r"(addr))

#define MMA_BF16(d, a, b) \
    asm volatile("mma.sync.aligned.m16n8k16.row.col.f32.bf16.bf16.f32 " \
        "{%0,%1,%2,%3}, {%4,%5,%6,%7}, {%8,%9}, {%0,%1,%2,%3};" \
        : "+f"((d)[0]), "+f"((d)[1]), "+f"((d)[2]), "+f"((d)[3]) \
        : "r"((a)[0]), "r"((a)[1]), "r"((a)[2]), "r"((a)[3]), \
          "r"((b)[0]), "r"((b)[1]))

#define CP_ASYNC16(dst, src) \
    asm volatile("cp.async.cg.shared.global [%0], [%1], 16;" \
        :: "r"(dst), "l"(src))
#define CP_COMMIT() asm volatile("cp.async.commit_group;" ::: "memory")
#define CP_WAIT0()  asm volatile("cp.async.wait_group 0;" ::: "memory")
#define CP_WAIT1()  asm volatile("cp.async.wait_group 1;" ::: "memory")

__device__ __forceinline__ uint32_t pack_bf16(float lo, float hi) {
    __nv_bfloat162 t = __float22bfloat162_rn(make_float2(lo, hi));
    return *reinterpret_cast<uint32_t*>(&t);
}

__device__ __forceinline__ void pack_split(float v0, float v1,
                                           uint32_t& ph, uint32_t& pl) {
    ph = pack_bf16(v0, v1);
    __nv_bfloat162 hb = *reinterpret_cast<__nv_bfloat162*>(&ph);
    pl = pack_bf16(v0 - __bfloat162float(hb.x), v1 - __bfloat162float(hb.y));
}

// ---------------------------------------------------------------------------
// Batched split (x + 4 weights in one launch)
// ---------------------------------------------------------------------------
struct SplitArgs {
    const float*   in[5];
    __nv_bfloat16* hi[5];
    __nv_bfloat16* lo[5];
    int            n4[5];
};

__device__ __forceinline__ void split_one(const float* __restrict__ in,
                                          __nv_bfloat16* __restrict__ hi,
                                          __nv_bfloat16* __restrict__ lo, int i)
{
    float4 v = reinterpret_cast<const float4*>(in)[i];
    uint32_t ph0, pl0, ph1, pl1;
    pack_split(v.x, v.y, ph0, pl0);
    pack_split(v.z, v.w, ph1, pl1);
    reinterpret_cast<uint2*>(hi)[i] = make_uint2(ph0, ph1);
    reinterpret_cast<uint2*>(lo)[i] = make_uint2(pl0, pl1);
}

__global__ void split_all(SplitArgs a)
{
    int seg = blockIdx.y;
    int i   = blockIdx.x * blockDim.x + threadIdx.x;
    if (i >= a.n4[seg]) return;
    split_one(a.in[seg], a.hi[seg], a.lo[seg], i);
}

// ---------------------------------------------------------------------------
// rope_k: k rope + split (standalone; measured ~6 us)
// ---------------------------------------------------------------------------
__global__ void rope_k(const float* __restrict__ k,
                       const float* __restrict__ c,
                       const float* __restrict__ s,
                       __nv_bfloat16* __restrict__ kh,
                       __nv_bfloat16* __restrict__ kl)
{
    int idx = blockIdx.x * blockDim.x + threadIdx.x;
    int n = BB * TT * KVH * 32;
    if (idx >= n) return;

    int d  = idx & 31;
    int r  = idx >> 5;
    int h  = r % KVH;
    int bt = r / KVH;

    const float* p  = k + ((size_t)bt * KVH + h) * 64;
    const float* cp = c + (size_t)bt * 64;
    const float* sp = s + (size_t)bt * 64;

    float x1 = p[d];
    float x2 = p[d + 32];
    float y1 = x1 * cp[d]      - x2 * sp[d];
    float y2 = x2 * cp[d + 32] + x1 * sp[d + 32];

    size_t o = ((size_t)bt * KVH + h) * 64;
    __nv_bfloat16 h1 = __float2bfloat16(y1);
    __nv_bfloat16 h2 = __float2bfloat16(y2);
    kh[o + d]      = h1;
    kh[o + d + 32] = h2;
    kl[o + d]      = __float2bfloat16(y1 - __bfloat162float(h1));
    kl[o + d + 32] = __float2bfloat16(y2 - __bfloat162float(h2));
}

// ---------------------------------------------------------------------------
// mma.sync GEMM body (R11 config): 256 threads, 8 warps 2x4, warp tile 64x32.
// Epilogues: fp32 C | bf16 hi/lo split (Ch != nullptr).
// ---------------------------------------------------------------------------
#define TILE_BYTES   10240
#define BUF_BYTES    (4*TILE_BYTES)
#define GEMM_SMEM    (2*BUF_BYTES)

#define SCALE_L2E 0.180336879f         // 0.125 * log2(e)

__device__ __forceinline__ void issue_tile(
    uint32_t sbuf,
    const __nv_bfloat16* __restrict__ Ahi, const __nv_bfloat16* __restrict__ Alo,
    const __nv_bfloat16* __restrict__ Bhi, const __nv_bfloat16* __restrict__ Blo,
    int m0, int n0, int k0, int K, int tid)
{
    #pragma unroll
    for (int it = 0; it < 2; it++) {
        int idx = tid + it * 256;
        int r   = idx >> 2;
        int c8  = idx & 3;
        uint32_t so = (uint32_t)(r * 80 + c8 * 16);
        size_t ga = (size_t)(m0 + r) * K + k0 + c8 * 8;
        size_t gb = (size_t)(n0 + r) * K + k0 + c8 * 8;
        CP_ASYNC16(sbuf + so,                 (const char*)(Ahi + ga));
        CP_ASYNC16(sbuf + TILE_BYTES + so,    (const char*)(Alo + ga));
        CP_ASYNC16(sbuf + 2*TILE_BYTES + so,  (const char*)(Bhi + gb));
        CP_ASYNC16(sbuf + 3*TILE_BYTES + so,  (const char*)(Blo + gb));
    }
}

__device__ __forceinline__ void gemm_body(
    uint32_t sbase,
    const __nv_bfloat16* __restrict__ Ahi, const __nv_bfloat16* __restrict__ Alo,
    const __nv_bfloat16* __restrict__ Bhi, const __nv_bfloat16* __restrict__ Blo,
    float* __restrict__ C,
    __nv_bfloat16* __restrict__ Ch, __nv_bfloat16* __restrict__ Cl,
    int M, int N, int K, int m0, int n0)
{
    const int tid  = threadIdx.x;
    const int lane = tid & 31;
    const int wid  = tid >> 5;
    const int wm   = wid >> 2;
    const int wn   = wid & 3;

    float acc[4][4][4];
    #pragma unroll
    for (int i = 0; i < 4; i++)
        #pragma unroll
        for (int j = 0; j < 4; j++)
            #pragma unroll
            for (int r = 0; r < 4; r++) acc[i][j][r] = 0.f;

    const uint32_t a_row  = (uint32_t)(wm * 64 + (lane & 15));
    const uint32_t a_k8   = (uint32_t)(lane >> 4);
    const uint32_t b_row  = (uint32_t)(wn * 32 + (lane & 7) + ((lane >> 4) << 3));
    const uint32_t b_k8   = (uint32_t)((lane >> 3) & 1);

    const int NK = K / 32;
    issue_tile(sbase, Ahi, Alo, Bhi, Blo, m0, n0, 0, K, tid);
    CP_COMMIT();

    for (int kt = 0; kt < NK; kt++) {
        CP_WAIT0();
        __syncthreads();
        if (kt + 1 < NK) {
            issue_tile(sbase + (uint32_t)((kt + 1) & 1) * BUF_BYTES,
                       Ahi, Alo, Bhi, Blo, m0, n0, (kt + 1) * 32, K, tid);
            CP_COMMIT();
        }
        const uint32_t buf = sbase + (uint32_t)(kt & 1) * BUF_BYTES;

        #pragma unroll
        for (int ks = 0; ks < 2; ks++) {
            uint32_t ah[4][4], al[4][4], bh[2][4], bl[2][4];
            #pragma unroll
            for (int mb = 0; mb < 4; mb++) {
                uint32_t addr = buf + (a_row + mb * 16) * 80
                                    + (ks * 2 + a_k8) * 16;
                LDSM4(ah[mb], addr);
                LDSM4(al[mb], addr + TILE_BYTES);
            }
            #pragma unroll
            for (int nb = 0; nb < 2; nb++) {
                uint32_t addr = buf + 2*TILE_BYTES
                                    + (b_row + nb * 16) * 80
                                    + (ks * 2 + b_k8) * 16;
                LDSM4(bh[nb], addr);
                LDSM4(bl[nb], addr + TILE_BYTES);
            }
            #pragma unroll
            for (int mb = 0; mb < 4; mb++) {
                #pragma unroll
                for (int n8 = 0; n8 < 4; n8++) {
                    uint32_t* Bh = &bh[n8 >> 1][(n8 & 1) * 2];
                    uint32_t* Bl = &bl[n8 >> 1][(n8 & 1) * 2];
                    MMA_BF16(acc[mb][n8], ah[mb], Bh);
                    MMA_BF16(acc[mb][n8], ah[mb], Bl);
                    MMA_BF16(acc[mb][n8], al[mb], Bh);
                }
            }
        }
    }

    if (Ch) {
        #pragma unroll
        for (int mb = 0; mb < 4; mb++) {
            int row = m0 + wm * 64 + mb * 16 + (lane >> 2);
            #pragma unroll
            for (int n8 = 0; n8 < 4; n8++) {
                int col = n0 + wn * 32 + n8 * 8 + (lane & 3) * 2;
                uint32_t ph, pl;
                pack_split(acc[mb][n8][0], acc[mb][n8][1], ph, pl);
                *reinterpret_cast<uint32_t*>(&Ch[(size_t)row * N + col]) = ph;
                *reinterpret_cast<uint32_t*>(&Cl[(size_t)row * N + col]) = pl;
                pack_split(acc[mb][n8][2], acc[mb][n8][3], ph, pl);
                *reinterpret_cast<uint32_t*>(&Ch[(size_t)(row + 8) * N + col]) = ph;
                *reinterpret_cast<uint32_t*>(&Cl[(size_t)(row + 8) * N + col]) = pl;
            }
        }
    } else {
        #pragma unroll
        for (int mb = 0; mb < 4; mb++) {
            int row = m0 + wm * 64 + mb * 16 + (lane >> 2);
            #pragma unroll
            for (int n8 = 0; n8 < 4; n8++) {
                int col = n0 + wn * 32 + n8 * 8 + (lane & 3) * 2;
                *reinterpret_cast<float2*>(&C[(size_t)row * N + col]) =
                    make_float2(acc[mb][n8][0], acc[mb][n8][1]);
                *reinterpret_cast<float2*>(&C[(size_t)(row + 8) * N + col]) =
                    make_float2(acc[mb][n8][2], acc[mb][n8][3]);
            }
        }
    }
}

__global__ __launch_bounds__(256) void gemm_mma(
    const __nv_bfloat16* __restrict__ Ahi, const __nv_bfloat16* __restrict__ Alo,
    const __nv_bfloat16* __restrict__ Bhi, const __nv_bfloat16* __restrict__ Blo,
    float* __restrict__ C, int M, int N, int K)
{
    extern __shared__ char sm[];
    gemm_body(smem_u32(sm), Ahi, Alo, Bhi, Blo, C, nullptr, nullptr,
              M, N, K, blockIdx.y * 128, blockIdx.x * 128);
}

// combined Q/K/V projections (R11 layout): Q fp32, K fp32, V bf16-split
__global__ __launch_bounds__(256) void gemm_mma_qkv(
    const __nv_bfloat16* __restrict__ Ahi, const __nv_bfloat16* __restrict__ Alo,
    const __nv_bfloat16* __restrict__ Wqh, const __nv_bfloat16* __restrict__ Wql,
    const __nv_bfloat16* __restrict__ Wkh, const __nv_bfloat16* __restrict__ Wkl,
    const __nv_bfloat16* __restrict__ Wvh, const __nv_bfloat16* __restrict__ Wvl,
    float* __restrict__ Cq, float* __restrict__ Ck,
    __nv_bfloat16* __restrict__ Vh, __nv_bfloat16* __restrict__ Vl)
{
    extern __shared__ char sm[];
    int bx = blockIdx.x;
    if (bx < 8) {
        gemm_body(smem_u32(sm), Ahi, Alo, Wqh, Wql, Cq, nullptr, nullptr,
                  MM, EE, EE, blockIdx.y * 128, bx * 128);
    } else if (bx < 10) {
        gemm_body(smem_u32(sm), Ahi, Alo, Wkh, Wkl, Ck, nullptr, nullptr,
                  MM, KVH * HD, EE, blockIdx.y * 128, (bx - 8) * 128);
    } else {
        gemm_body(smem_u32(sm), Ahi, Alo, Wvh, Wvl, nullptr, Vh, Vl,
                  MM, KVH * HD, EE, blockIdx.y * 128, (bx - 10) * 128);
    }
}

// ---------------------------------------------------------------------------
// Flash attention: 1 head/CTA, bf16 hi/lo split, 4 warps, 3 CTAs/SM.
// Register Q-RoPE (with SCALE_L2E folded in), no-max base-2 softmax
// (MUFU ex2), deferred-l reduction, interleaved MMA issue.
// ---------------------------------------------------------------------------
#define FROW      144
#define FARR      (64*FROW)
#define KVBUF     (4*FARR)
#define OFF_KH    0
#define OFF_KL    FARR
#define OFF_VH    (2*FARR)
#define OFF_VL    (3*FARR)
#define SM_QH     KVBUF                // bf16 hi; lo at +FARR (buffer-1 overlay)
#define FLASH_SMEM (8*FARR)            // 73728; 3 CTAs/SM

__device__ __forceinline__ void flash_load_kv(
    uint32_t kb,
    const __nv_bfloat16* __restrict__ kh, const __nv_bfloat16* __restrict__ kl,
    const __nv_bfloat16* __restrict__ vh, const __nv_bfloat16* __restrict__ vl,
    int b, int kt, int kvh, int tid)
{
    #pragma unroll
    for (int it = 0; it < 4; it++) {
        int idx = tid + it * 128;
        int r   = idx >> 3;
        int c   = idx & 7;
        size_t g = (size_t)(b * TT + kt * 64 + r) * (KVH * HD) + kvh * 64 + c * 8;
        uint32_t so = (uint32_t)(r * FROW + c * 16);
        CP_ASYNC16(kb + OFF_KH + so, (const char*)(kh + g));
        CP_ASYNC16(kb + OFF_KL + so, (const char*)(kl + g));
        CP_ASYNC16(kb + OFF_VH + so, (const char*)(vh + g));
        CP_ASYNC16(kb + OFF_VL + so, (const char*)(vl + g));
    }
}

__global__ __launch_bounds__(128, 3) void flash_mma(
    const float* __restrict__ qf,
    const float* __restrict__ cs, const float* __restrict__ sn,
    const __nv_bfloat16* __restrict__ kh, const __nv_bfloat16* __restrict__ kl,
    const __nv_bfloat16* __restrict__ vh, const __nv_bfloat16* __restrict__ vl,
    __nv_bfloat16* __restrict__ yh, __nv_bfloat16* __restrict__ yl)
{
    extern __shared__ char sm[];
    const uint32_t sb = smem_u32(sm);
    const int tid  = threadIdx.x;
    const int lane = tid & 31;
    const int wid  = tid >> 5;
    const int qt   = (int)(gridDim.x - 1 - blockIdx.x);
    const int h    = blockIdx.y;
    const int b    = blockIdx.z;
    const int kvh  = h / GG;

    flash_load_kv(sb, kh, kl, vh, vl, b, 0, kvh, tid);
    CP_COMMIT();

    // Q RoPE in registers (SCALE_L2E folded): row r = tid>>1, half s2 = tid&1
    {
        int r  = tid >> 1;
        int s2 = tid & 1;
        size_t qrow = (size_t)(b * TT + qt * 64 + r) * EE + h * 64 + s2 * 16;
        size_t crow = (size_t)(b * TT + qt * 64 + r) * 64 + s2 * 16;
        float4 x1v[4], x2v[4], c1v[4], c2v[4], s1v[4], s2v[4];
        #pragma unroll
        for (int j = 0; j < 4; j++) {
            x1v[j] = *reinterpret_cast<const float4*>(qf + qrow + 4 * j);
            x2v[j] = *reinterpret_cast<const float4*>(qf + qrow + 32 + 4 * j);
            c1v[j] = *reinterpret_cast<const float4*>(cs + crow + 4 * j);
            c2v[j] = *reinterpret_cast<const float4*>(cs + crow + 32 + 4 * j);
            s1v[j] = *reinterpret_cast<const float4*>(sn + crow + 4 * j);
            s2v[j] = *reinterpret_cast<const float4*>(sn + crow + 32 + 4 * j);
        }
        uint32_t* qhr = reinterpret_cast<uint32_t*>(sm + SM_QH + r * FROW + s2 * 32);
        uint32_t* qlr = reinterpret_cast<uint32_t*>(sm + SM_QH + FARR + r * FROW + s2 * 32);
        #pragma unroll
        for (int j = 0; j < 4; j++) {
            const float* x1 = &x1v[j].x;
            const float* x2 = &x2v[j].x;
            const float* c1 = &c1v[j].x;
            const float* c2 = &c2v[j].x;
            const float* z1 = &s1v[j].x;
            const float* z2 = &s2v[j].x;
            float y1[4], y2[4];
            #pragma unroll
            for (int e = 0; e < 4; e++) {
                y1[e] = (x1[e] * c1[e] - x2[e] * z1[e]) * SCALE_L2E;
                y2[e] = (x2[e] * c2[e] + x1[e] * z2[e]) * SCALE_L2E;
            }
            uint32_t ph, pl;
            pack_split(y1[0], y1[1], ph, pl);
            qhr[2 * j]     = ph;  qlr[2 * j]     = pl;
            pack_split(y1[2], y1[3], ph, pl);
            qhr[2 * j + 1] = ph;  qlr[2 * j + 1] = pl;
            pack_split(y2[0], y2[1], ph, pl);
            qhr[16 + 2 * j]     = ph;  qlr[16 + 2 * j]     = pl;
            pack_split(y2[2], y2[3], ph, pl);
            qhr[16 + 2 * j + 1] = ph;  qlr[16 + 2 * j + 1] = pl;
        }
    }
    __syncthreads();

    uint32_t qfh[4][4], qfl[4][4];
    {
        const uint32_t a_row = (uint32_t)(wid * 16 + (lane & 15));
        const uint32_t a_k8  = (uint32_t)(lane >> 4);
        #pragma unroll
        for (int ks = 0; ks < 4; ks++) {
            uint32_t addr = sb + SM_QH + a_row * FROW + (ks * 2 + a_k8) * 16;
            LDSM4(qfh[ks], addr);
            LDSM4(qfl[ks], addr + FARR);
        }
    }
    __syncthreads();     // buffer-1 region free after this

    const uint32_t kb_row = (uint32_t)((lane & 7) + ((lane >> 4) << 3));
    const uint32_t kb_k8  = (uint32_t)((lane >> 3) & 1);
    const uint32_t vb_row = (uint32_t)((lane & 7) + (((lane >> 3) & 1) << 3));
    const uint32_t vb_col = (uint32_t)((lane >> 4) << 3);

    float oacc[8][4];
    #pragma unroll
    for (int nb = 0; nb < 8; nb++)
        #pragma unroll
        for (int j = 0; j < 4; j++) oacc[nb][j] = 0.f;
    float l0p = 0.f, l1p = 0.f;      // per-thread partials

    int cur = 0;
    for (int kt = 0; kt <= qt; kt++) {
        if (kt + 1 <= qt) {
            flash_load_kv(sb + (uint32_t)(cur ^ 1) * KVBUF,
                          kh, kl, vh, vl, b, kt + 1, kvh, tid);
            CP_COMMIT();
            CP_WAIT1();
        } else {
            CP_WAIT0();
        }
        __syncthreads();
        const uint32_t kvb = sb + (uint32_t)cur * KVBUF;
        const bool diag = (kt == qt);

        float sacc[8][4];
        #pragma unroll
        for (int nb = 0; nb < 8; nb++)
            #pragma unroll
            for (int j = 0; j < 4; j++) sacc[nb][j] = 0.f;

        #pragma unroll
        for (int ks = 0; ks < 4; ks++) {
            #pragma unroll
            for (int nb = 0; nb < 4; nb++) {
                if (diag && nb > wid) continue;
                uint32_t addr = kvb + OFF_KH + (kb_row + nb * 16) * FROW
                                            + (ks * 2 + kb_k8) * 16;
                uint32_t bh[4], bl[4];
                LDSM4(bh, addr);
                LDSM4(bl, addr + FARR);
                MMA_BF16(sacc[2*nb],   qfh[ks], bh);
                MMA_BF16(sacc[2*nb+1], qfh[ks], bh + 2);
                MMA_BF16(sacc[2*nb],   qfh[ks], bl);
                MMA_BF16(sacc[2*nb+1], qfh[ks], bl + 2);
                MMA_BF16(sacc[2*nb],   qfl[ks], bh);
                MMA_BF16(sacc[2*nb+1], qfl[ks], bh + 2);
            }
        }

        // causal mask (S already base-2 scaled via pre-scaled Q)
        if (diag) {
            #pragma unroll
            for (int nb = 0; nb < 8; nb++)
                #pragma unroll
                for (int j = 0; j < 4; j++) {
                    int n_loc = nb * 8 + 2 * (lane & 3) + (j & 1);
                    int m_loc = wid * 16 + (lane >> 2) + ((j >> 1) << 3);
                    if (n_loc > m_loc) sacc[nb][j] = -1e30f;
                }
        }

        // no-max softmax: exp2 + per-thread partial sums
        float sum0 = 0.f, sum1 = 0.f;
        #pragma unroll
        for (int nb = 0; nb < 8; nb++) {
            sacc[nb][0] = ex2f(sacc[nb][0]);
            sacc[nb][1] = ex2f(sacc[nb][1]);
            sacc[nb][2] = ex2f(sacc[nb][2]);
            sacc[nb][3] = ex2f(sacc[nb][3]);
            sum0 += sacc[nb][0] + sacc[nb][1];
            sum1 += sacc[nb][2] + sacc[nb][3];
        }
        l0p += sum0;
        l1p += sum1;

        // streamed pack + PV
        #pragma unroll
        for (int j16 = 0; j16 < 4; j16++) {
            if (diag && j16 > wid) continue;
            uint32_t pfh[4], pfl[4];
            {
                float* c0 = sacc[2*j16];
                float* c1 = sacc[2*j16 + 1];
                #pragma unroll
                for (int a = 0; a < 4; a++) {
                    float v0 = (a < 2) ? c0[(a & 1) * 2]     : c1[(a & 1) * 2];
                    float v1 = (a < 2) ? c0[(a & 1) * 2 + 1] : c1[(a & 1) * 2 + 1];
                    pack_split(v0, v1, pfh[a], pfl[a]);
                }
            }
            #pragma unroll
            for (int nb = 0; nb < 4; nb++) {
                uint32_t addr = kvb + OFF_VH
                              + (j16 * 16 + vb_row) * FROW
                              + (nb * 16 + vb_col) * 2;
                uint32_t vhf[4], vlf[4];
                LDSM4T(vhf, addr);
                LDSM4T(vlf, addr + FARR);
                MMA_BF16(oacc[2*nb],   pfh, vhf);
                MMA_BF16(oacc[2*nb+1], pfh, vhf + 2);
                MMA_BF16(oacc[2*nb],   pfh, vlf);
                MMA_BF16(oacc[2*nb+1], pfh, vlf + 2);
                MMA_BF16(oacc[2*nb],   pfl, vhf);
                MMA_BF16(oacc[2*nb+1], pfl, vhf + 2);
            }
        }

        __syncthreads();
        cur ^= 1;
    }

    // deferred l reduction (once)
    l0p += __shfl_xor_sync(0xffffffffu, l0p, 1);
    l0p += __shfl_xor_sync(0xffffffffu, l0p, 2);
    l1p += __shfl_xor_sync(0xffffffffu, l1p, 1);
    l1p += __shfl_xor_sync(0xffffffffu, l1p, 2);

    float inv0 = 1.f / l0p, inv1 = 1.f / l1p;
    size_t row0 = (size_t)(b * TT + qt * 64 + wid * 16 + (lane >> 2));
    #pragma unroll
    for (int nb = 0; nb < 8; nb++) {
        size_t col = (size_t)(h * 64 + nb * 8 + 2 * (lane & 3));
        uint32_t ph, pl;
        pack_split(oacc[nb][0] * inv0, oacc[nb][1] * inv0, ph, pl);
        *reinterpret_cast<uint32_t*>(&yh[row0 * EE + col]) = ph;
        *reinterpret_cast<uint32_t*>(&yl[row0 * EE + col]) = pl;
        pack_split(oacc[nb][2] * inv1, oacc[nb][3] * inv1, ph, pl);
        *reinterpret_cast<uint32_t*>(&yh[(row0 + 8) * EE + col]) = ph;
        *reinterpret_cast<uint32_t*>(&yl[(row0 + 8) * EE + col]) = pl;
    }
}

// ---------------------------------------------------------------------------
// kernel_launch — 5 launches (R11 structure); flash is #4 (profiler window)
// ---------------------------------------------------------------------------
extern "C" void kernel_launch(void* const* d_in, const int* in_sizes, int n_in,
                              void* d_out, int out_size)
{
    const float* x   = (const float*)d_in[0];
    const float* cs  = (const float*)d_in[1];
    const float* sn  = (const float*)d_in[2];
    const float* Wq  = (const float*)d_in[3];
    const float* Wk  = (const float*)d_in[4];
    const float* Wv  = (const float*)d_in[5];
    const float* Wo  = (const float*)d_in[6];
    float* out = (float*)d_out;

    float *q, *k;
    cudaGetSymbolAddress((void**)&q, g_q);
    cudaGetSymbolAddress((void**)&k, g_k);

    __nv_bfloat16 *xh, *xl, *yh, *yl;
    __nv_bfloat16 *wqh, *wql, *wkh, *wkl, *wvh, *wvl, *woh, *wol;
    __nv_bfloat16 *khp, *klp, *vhp, *vlp;
    cudaGetSymbolAddress((void**)&xh,  g_x_hi);  cudaGetSymbolAddress((void**)&xl,  g_x_lo);
    cudaGetSymbolAddress((void**)&yh,  g_y_hi);  cudaGetSymbolAddress((void**)&yl,  g_y_lo);
    cudaGetSymbolAddress((void**)&wqh, g_wq_hi); cudaGetSymbolAddress((void**)&wql, g_wq_lo);
    cudaGetSymbolAddress((void**)&wkh, g_wk_hi); cudaGetSymbolAddress((void**)&wkl, g_wk_lo);
    cudaGetSymbolAddress((void**)&wvh, g_wv_hi); cudaGetSymbolAddress((void**)&wvl, g_wv_lo);
    cudaGetSymbolAddress((void**)&woh, g_wo_hi); cudaGetSymbolAddress((void**)&wol, g_wo_lo);
    cudaGetSymbolAddress((void**)&khp, g_kh);    cudaGetSymbolAddress((void**)&klp, g_kl);
    cudaGetSymbolAddress((void**)&vhp, g_vh);    cudaGetSymbolAddress((void**)&vlp, g_vl);

    cudaFuncSetAttribute(gemm_mma, cudaFuncAttributeMaxDynamicSharedMemorySize,
                         GEMM_SMEM);
    cudaFuncSetAttribute(gemm_mma_qkv, cudaFuncAttributeMaxDynamicSharedMemorySize,
                         GEMM_SMEM);
    cudaFuncSetAttribute(flash_mma, cudaFuncAttributeMaxDynamicSharedMemorySize,
                         FLASH_SMEM);

    // #1: all input splits
    {
        SplitArgs a;
        a.in[0] = x;  a.hi[0] = xh;  a.lo[0] = xl;  a.n4[0] = MM * EE / 4;
        a.in[1] = Wq; a.hi[1] = wqh; a.lo[1] = wql; a.n4[1] = EE * EE / 4;
        a.in[2] = Wk; a.hi[2] = wkh; a.lo[2] = wkl; a.n4[2] = KVH * HD * EE / 4;
        a.in[3] = Wv; a.hi[3] = wvh; a.lo[3] = wvl; a.n4[3] = KVH * HD * EE / 4;
        a.in[4] = Wo; a.hi[4] = woh; a.lo[4] = wol; a.n4[4] = EE * EE / 4;
        int maxb = (MM * EE / 4 + 255) / 256;
        split_all<<<dim3(maxb, 5), 256>>>(a);
    }

    // #2: Q + K + V projections (Q fp32, K fp32, V bf16-split)
    gemm_mma_qkv<<<dim3(12, MM / 128), 256, GEMM_SMEM>>>(
        xh, xl, wqh, wql, wkh, wkl, wvh, wvl, q, k, vhp, vlp);

    // #3: k rope + split
    {
        int n = BB * TT * KVH * 32;
        rope_k<<<(n + 255) / 256, 256>>>(k, cs, sn, khp, klp);
    }

    // #4: flash attention — profiler window
    flash_mma<<<dim3(TT / 64, HH, BB), 128, FLASH_SMEM>>>(
        q, cs, sn, khp, klp, vhp, vlp, yh, yl);

    // #5: output projection
    gemm_mma<<<dim3(EE / 128, MM / 128), 256, GEMM_SMEM>>>(yh, yl, woh, wol, out, MM, EE, EE);
}